// round 2
// baseline (speedup 1.0000x reference)
#include <cuda_runtime.h>
#include <cuda_bf16.h>

// Dempster-Shafer evidential layer, closed-form commonality formulation.
// x: [B=2, C=16, H=64, W=64, D=64] f32
// W: [K=20, C=16], BETA: [K,4], alpha: [K,1], gamma: [K,1]
// out: [B, M+1=5, H, W, D] f32
//
// Per point p:
//   d_k   = 0.5*||x_p - W_k||^2 = 0.5*||x||^2 - <x,W_k> + 0.5*||W_k||^2
//   s_k   = alphap_k * exp(-gamma_k^2 * d_k)
//   Q_m   = prod_k (U[k][m]*s_k + (1-s_k))     (commonality, multiplicative)
//   O     = prod_k (1-s_k)
//   f_m   = Q_m - O ; normalize [f_0..f_3, O]

#define CC   16
#define KK   20
#define MM   4
#define HWD  (64*64*64)
#define NPTS (2*HWD)

__global__ __launch_bounds__(256) void ds_kernel(
    const float* __restrict__ x,
    const float* __restrict__ Wp,
    const float* __restrict__ BETA,
    const float* __restrict__ alpha,
    const float* __restrict__ gamma,
    float* __restrict__ out)
{
    // per-block derived constants (cheap: ~1.8KB smem, trivial compute)
    __shared__ float sW[CC][KK];   // transposed W: sW[c][k]
    __shared__ float sU[KK][MM];   // membership weights
    __shared__ float sAp[KK];      // alphap
    __shared__ float sGn[KK];      // -gamma^2
    __shared__ float sHw2[KK];     // 0.5*||W_k||^2

    const int tid = threadIdx.x;

    for (int i = tid; i < CC * KK; i += blockDim.x) {
        int k = i % KK, c = i / KK;
        sW[c][k] = Wp[k * CC + c];
    }
    if (tid < KK) {
        const int k = tid;
        float w2 = 0.f;
        #pragma unroll
        for (int c = 0; c < CC; c++) { float v = Wp[k * CC + c]; w2 = fmaf(v, v, w2); }
        sHw2[k] = 0.5f * w2;
        float a = alpha[k];
        sAp[k] = 0.99f / (1.0f + __expf(-a));
        float g = gamma[k];
        sGn[k] = -(g * g);
        float b2[MM]; float bs = 0.f;
        #pragma unroll
        for (int m = 0; m < MM; m++) { float b = BETA[k * MM + m]; b2[m] = b * b; bs += b2[m]; }
        float inv = __fdividef(1.0f, bs);
        #pragma unroll
        for (int m = 0; m < MM; m++) sU[k][m] = b2[m] * inv;
    }
    __syncthreads();

    const int p = blockIdx.x * 256 + tid;   // NPTS is an exact multiple of 256
    const int b  = p >> 18;                 // / HWD
    const int sp = p & (HWD - 1);
    const float* xb = x + (size_t)b * CC * HWD + sp;

    // xw[k] = <x, W_k>, x2 = ||x||^2  — 20 independent 16-deep FMA chains
    float xw[KK];
    #pragma unroll
    for (int k = 0; k < KK; k++) xw[k] = 0.f;
    float x2 = 0.f;

    #pragma unroll
    for (int c = 0; c < CC; c++) {
        float xc = __ldg(xb + (size_t)c * HWD);
        x2 = fmaf(xc, xc, x2);
        #pragma unroll
        for (int k = 0; k < KK; k++) xw[k] = fmaf(xc, sW[c][k], xw[k]);
    }

    const float h = 0.5f * x2;
    float P0 = 1.f, P1 = 1.f, P2 = 1.f, P3 = 1.f, O = 1.f;

    #pragma unroll
    for (int k = 0; k < KK; k++) {
        float d   = (h - xw[k]) + sHw2[k];
        float s   = sAp[k] * __expf(sGn[k] * d);
        float oms = 1.0f - s;
        O  *= oms;
        P0 *= fmaf(sU[k][0], s, oms);
        P1 *= fmaf(sU[k][1], s, oms);
        P2 *= fmaf(sU[k][2], s, oms);
        P3 *= fmaf(sU[k][3], s, oms);
    }

    float f0 = P0 - O, f1 = P1 - O, f2 = P2 - O, f3 = P3 - O;
    float sum = ((f0 + f1) + (f2 + f3)) + O;
    float inv = __fdividef(1.0f, sum);

    float* ob = out + (size_t)b * (MM + 1) * HWD + sp;
    ob[0 * HWD] = f0 * inv;
    ob[1 * HWD] = f1 * inv;
    ob[2 * HWD] = f2 * inv;
    ob[3 * HWD] = f3 * inv;
    ob[4 * HWD] = O  * inv;
}

extern "C" void kernel_launch(void* const* d_in, const int* in_sizes, int n_in,
                              void* d_out, int out_size)
{
    const float* x     = (const float*)d_in[0];
    const float* Wp    = (const float*)d_in[1];
    const float* BETA  = (const float*)d_in[2];
    const float* alpha = (const float*)d_in[3];
    const float* gamma = (const float*)d_in[4];
    float* out = (float*)d_out;

    ds_kernel<<<NPTS / 256, 256>>>(x, Wp, BETA, alpha, gamma, out);
}

// round 3
// speedup vs baseline: 1.1168x; 1.1168x over previous
#include <cuda_runtime.h>

// Dempster-Shafer evidential layer — packed f32x2 formulation, 2 points/thread.
// x: [B=2, C=16, 64,64,64] f32;  W: [20,16];  BETA: [20,4];  alpha,gamma: [20,1]
// out: [B, 5, 64,64,64] f32
//
// Per point: d_k = 0.5||x||^2 - <x,W_k> + 0.5||W_k||^2
//            s_k = alphap_k * 2^(gn_k * d_k)          (gn = -gamma^2 * log2e)
//            Q_m = prod_k (U[k][m]*s_k + (1-s_k)),  O = prod_k (1-s_k)
//            out = normalize([Q_m - O, O])

#define CC   16
#define KK   20
#define MM   4
#define HWD  (64*64*64)        // 262144
#define HHWD (HWD/2)           // 131072 pairs per volume
#define NPAIRS (2*HHWD)        // 262144 thread-points (pairs)

typedef unsigned long long u64;

__device__ __forceinline__ u64 fma2(u64 a, u64 b, u64 c) {
    u64 d; asm("fma.rn.f32x2 %0, %1, %2, %3;" : "=l"(d) : "l"(a), "l"(b), "l"(c)); return d;
}
__device__ __forceinline__ u64 mul2(u64 a, u64 b) {
    u64 d; asm("mul.rn.f32x2 %0, %1, %2;" : "=l"(d) : "l"(a), "l"(b)); return d;
}
__device__ __forceinline__ u64 add2(u64 a, u64 b) {
    u64 d; asm("add.rn.f32x2 %0, %1, %2;" : "=l"(d) : "l"(a), "l"(b)); return d;
}
__device__ __forceinline__ u64 pk(float lo, float hi) {
    u64 r; asm("mov.b64 %0, {%1,%2};" : "=l"(r) : "f"(lo), "f"(hi)); return r;
}
__device__ __forceinline__ void upk(u64 v, float& lo, float& hi) {
    asm("mov.b64 {%0,%1}, %2;" : "=f"(lo), "=f"(hi) : "l"(v));
}
__device__ __forceinline__ float ex2f(float x) {
    float r; asm("ex2.approx.f32 %0, %1;" : "=f"(r) : "f"(x)); return r;
}
__device__ __forceinline__ float rcpf(float x) {
    float r; asm("rcp.approx.f32 %0, %1;" : "=f"(r) : "f"(x)); return r;
}

#define ONEp  0x3F8000003F800000ull
#define NEG1p 0xBF800000BF800000ull
#define HALFp 0x3F0000003F000000ull

__global__ __launch_bounds__(256) void ds_kernel(
    const float* __restrict__ x,
    const float* __restrict__ Wp,
    const float* __restrict__ BETA,
    const float* __restrict__ alpha,
    const float* __restrict__ gamma,
    float* __restrict__ out)
{
    // duplicated-packed constants: LDS.128 yields 2 ready f32x2 operands
    __shared__ ulonglong2 sW2[CC][KK / 2];   // (w,w) pairs, 2 k per vec
    __shared__ ulonglong2 sKC[KK][4];        // [gn,ngn][ghw2,ap][u0,u1][u2,u3]

    const int tid = threadIdx.x;

    {
        u64* wbase = (u64*)&sW2[0][0];       // row length = KK u64
        for (int i = tid; i < CC * KK; i += 256) {
            int k = i % KK, c = i / KK;
            float w = Wp[k * CC + c];
            wbase[c * KK + k] = pk(w, w);
        }
    }
    if (tid < KK) {
        const int k = tid;
        float w2 = 0.f;
        #pragma unroll
        for (int c = 0; c < CC; c++) { float v = Wp[k * CC + c]; w2 = fmaf(v, v, w2); }
        float g  = gamma[k];
        float gn = -(g * g) * 1.4426950408889634f;        // -gamma^2 * log2(e)
        float ghw2 = gn * 0.5f * w2;
        float a  = alpha[k];
        float ap = 0.99f * rcpf(1.0f + ex2f(-a * 1.4426950408889634f));
        float b2[MM]; float bs = 0.f;
        #pragma unroll
        for (int m = 0; m < MM; m++) { float b = BETA[k * MM + m]; b2[m] = b * b; bs += b2[m]; }
        float inv = __fdividef(1.0f, bs);
        sKC[k][0] = make_ulonglong2(pk(gn, gn), pk(-gn, -gn));
        sKC[k][1] = make_ulonglong2(pk(ghw2, ghw2), pk(ap, ap));
        sKC[k][2] = make_ulonglong2(pk(b2[0]*inv, b2[0]*inv), pk(b2[1]*inv, b2[1]*inv));
        sKC[k][3] = make_ulonglong2(pk(b2[2]*inv, b2[2]*inv), pk(b2[3]*inv, b2[3]*inv));
    }
    __syncthreads();

    const int pp  = blockIdx.x * 256 + tid;     // pair index
    const int b   = pp >> 17;                   // pair / HHWD
    const int spp = pp & (HHWD - 1);
    const u64* xb = (const u64*)x + (size_t)b * CC * HHWD + spp;

    // xw[k] = <x, W_k> for both points, packed. x2p = ||x||^2 packed.
    u64 xw[KK];
    #pragma unroll
    for (int k = 0; k < KK; k++) xw[k] = 0ull;
    u64 x2p = 0ull;

    #pragma unroll
    for (int c = 0; c < CC; c++) {
        u64 xc = __ldg(xb + (size_t)c * HHWD);  // LDG.64: both points' channel-c values
        x2p = fma2(xc, xc, x2p);
        #pragma unroll
        for (int k2 = 0; k2 < KK / 2; k2++) {
            ulonglong2 w = sW2[c][k2];          // LDS.128
            xw[2 * k2]     = fma2(xc, w.x, xw[2 * k2]);
            xw[2 * k2 + 1] = fma2(xc, w.y, xw[2 * k2 + 1]);
        }
    }

    const u64 hp = mul2(x2p, HALFp);            // 0.5*||x||^2, packed
    u64 O = ONEp, P0 = ONEp, P1 = ONEp, P2 = ONEp, P3 = ONEp;

    #pragma unroll
    for (int k = 0; k < KK; k++) {
        ulonglong2 q0 = sKC[k][0];
        ulonglong2 q1 = sKC[k][1];
        u64 t = fma2(q0.x, hp, q1.x);           // gn*h + gn*hw2
        t     = fma2(q0.y, xw[k], t);           // - gn*xw  -> log2-domain exponent
        float a0, a1; upk(t, a0, a1);
        u64 s = mul2(pk(ex2f(a0), ex2f(a1)), q1.y);
        u64 oms = fma2(s, NEG1p, ONEp);         // 1 - s
        ulonglong2 q2 = sKC[k][2];
        ulonglong2 q3 = sKC[k][3];
        O  = mul2(O, oms);
        P0 = mul2(P0, fma2(q2.x, s, oms));
        P1 = mul2(P1, fma2(q2.y, s, oms));
        P2 = mul2(P2, fma2(q3.x, s, oms));
        P3 = mul2(P3, fma2(q3.y, s, oms));
    }

    const u64 nO = mul2(O, NEG1p);
    u64 f0 = add2(P0, nO), f1 = add2(P1, nO), f2 = add2(P2, nO), f3 = add2(P3, nO);
    u64 sum = add2(add2(add2(f0, f1), add2(f2, f3)), O);
    float s0, s1; upk(sum, s0, s1);
    const u64 inv = pk(rcpf(s0), rcpf(s1));

    u64* ob = (u64*)out + (size_t)b * (MM + 1) * HHWD + spp;
    ob[0 * (size_t)HHWD] = mul2(f0, inv);
    ob[1 * (size_t)HHWD] = mul2(f1, inv);
    ob[2 * (size_t)HHWD] = mul2(f2, inv);
    ob[3 * (size_t)HHWD] = mul2(f3, inv);
    ob[4 * (size_t)HHWD] = mul2(O,  inv);
}

extern "C" void kernel_launch(void* const* d_in, const int* in_sizes, int n_in,
                              void* d_out, int out_size)
{
    const float* x     = (const float*)d_in[0];
    const float* Wp    = (const float*)d_in[1];
    const float* BETA  = (const float*)d_in[2];
    const float* alpha = (const float*)d_in[3];
    const float* gamma = (const float*)d_in[4];
    float* out = (float*)d_out;

    ds_kernel<<<NPAIRS / 256, 256>>>(x, Wp, BETA, alpha, gamma, out);
}